// round 2
// baseline (speedup 1.0000x reference)
#include <cuda_runtime.h>

#define N_NODES 50000
#define CH      256
#define N_EDGES 800000
#define NSCAN   196          // ceil(50000/256)

// ---------------- scratch (device globals) ------------------------------------
__device__ float g_xw  [N_NODES * CH];   // x @ conv_w  (51.2 MB, L2-resident)
__device__ float g_dinv[N_NODES];
__device__ int   g_sdeg[N_NODES];        // src degree (incl self-loop)
__device__ int   g_cnt [N_NODES];        // dst degree (excl self-loop)
__device__ int   g_rowptr[N_NODES];
__device__ int   g_cursor[N_NODES];
__device__ int   g_bsum[NSCAN];
__device__ int   g_csr_src [N_EDGES];
__device__ float g_csr_coef[N_EDGES];
__device__ float g_s[CH];

// ---------------- init ---------------------------------------------------------
__global__ void k_init0() {
    int i = blockIdx.x * blockDim.x + threadIdx.x;
    if (i < N_NODES) { g_sdeg[i] = 1; g_cnt[i] = 0; }
    if (i < CH)      g_s[i] = 0.0f;
}

// ---------------- histograms ----------------------------------------------------
__global__ void k_count(const int* __restrict__ src, const int* __restrict__ dst) {
    int e = blockIdx.x * blockDim.x + threadIdx.x;
    if (e < N_EDGES) {
        atomicAdd(&g_sdeg[src[e]], 1);
        atomicAdd(&g_cnt[dst[e]], 1);
    }
}

__global__ void k_dinv() {
    int i = blockIdx.x * blockDim.x + threadIdx.x;
    if (i < N_NODES) g_dinv[i] = rsqrtf((float)g_sdeg[i]);
}

// ---------------- 3-kernel exclusive scan over g_cnt ---------------------------
__global__ void k_scan1() {
    __shared__ int sh[256];
    int t = threadIdx.x, i = blockIdx.x * 256 + t;
    int v = (i < N_NODES) ? g_cnt[i] : 0;
    sh[t] = v; __syncthreads();
    #pragma unroll
    for (int off = 1; off < 256; off <<= 1) {
        int add = (t >= off) ? sh[t - off] : 0;
        __syncthreads();
        sh[t] += add;
        __syncthreads();
    }
    if (i < N_NODES) g_rowptr[i] = sh[t] - v;   // exclusive
    if (t == 255) g_bsum[blockIdx.x] = sh[255];
}

__global__ void k_scan2() {
    __shared__ int sh[256];
    int t = threadIdx.x;
    int v = (t < NSCAN) ? g_bsum[t] : 0;
    sh[t] = v; __syncthreads();
    #pragma unroll
    for (int off = 1; off < 256; off <<= 1) {
        int add = (t >= off) ? sh[t - off] : 0;
        __syncthreads();
        sh[t] += add;
        __syncthreads();
    }
    if (t < NSCAN) g_bsum[t] = sh[t] - v;       // exclusive
}

__global__ void k_scan3() {
    int i = blockIdx.x * blockDim.x + threadIdx.x;
    if (i < N_NODES) {
        int r = g_rowptr[i] + g_bsum[blockIdx.x * 256 / 256 == 0 ? 0 : 0];
        // note: proper block index below
        r = g_rowptr[i] + g_bsum[i >> 8];
        g_rowptr[i] = r;
        g_cursor[i] = r;
    }
}

// ---------------- CSR fill (also precompute edge coefficient) -------------------
__global__ void k_fill(const int* __restrict__ src, const int* __restrict__ dst) {
    int e = blockIdx.x * blockDim.x + threadIdx.x;
    if (e < N_EDGES) {
        int s = src[e], d = dst[e];
        int pos = atomicAdd(&g_cursor[d], 1);
        g_csr_src[pos]  = s;
        g_csr_coef[pos] = g_dinv[s] * g_dinv[d];
    }
}

// ---------------- SGEMM: g_xw[M,256] = x[M,256] @ W[256,256] -------------------
#define BM 128
#define BN 128
#define BK 16
__global__ void __launch_bounds__(256) k_gemm(const float* __restrict__ A,
                                              const float* __restrict__ W) {
    __shared__ float As[BK][BM];
    __shared__ float Bs[BK][BN];
    const int tid = threadIdx.x;
    const int bm = blockIdx.x * BM;
    const int bn = blockIdx.y * BN;

    const int a_row = tid >> 2;            // 0..63 (and +64)
    const int a_col = (tid & 3) << 2;      // 0,4,8,12
    const int b_row = tid >> 4;            // 0..15
    const int b_col = (tid & 15) << 3;     // 0..120 step 8

    const int ty = (tid >> 4) << 3;
    const int tx = (tid & 15) << 3;

    float acc[8][8];
    #pragma unroll
    for (int i = 0; i < 8; i++)
        #pragma unroll
        for (int j = 0; j < 8; j++) acc[i][j] = 0.f;

    for (int k0 = 0; k0 < CH; k0 += BK) {
        #pragma unroll
        for (int h = 0; h < 2; h++) {
            int r = a_row + h * 64;
            int gr = bm + r;
            float4 av = make_float4(0.f, 0.f, 0.f, 0.f);
            if (gr < N_NODES) av = *(const float4*)&A[gr * CH + k0 + a_col];
            As[a_col + 0][r] = av.x;
            As[a_col + 1][r] = av.y;
            As[a_col + 2][r] = av.z;
            As[a_col + 3][r] = av.w;
        }
        *(float4*)&Bs[b_row][b_col] =
            *(const float4*)&W[(k0 + b_row) * CH + bn + b_col];
        *(float4*)&Bs[b_row][b_col + 4] =
            *(const float4*)&W[(k0 + b_row) * CH + bn + b_col + 4];
        __syncthreads();
        #pragma unroll
        for (int k = 0; k < BK; k++) {
            float ar[8], br[8];
            #pragma unroll
            for (int i = 0; i < 8; i++) ar[i] = As[k][ty + i];
            #pragma unroll
            for (int j = 0; j < 8; j++) br[j] = Bs[k][tx + j];
            #pragma unroll
            for (int i = 0; i < 8; i++)
                #pragma unroll
                for (int j = 0; j < 8; j++) acc[i][j] += ar[i] * br[j];
        }
        __syncthreads();
    }
    #pragma unroll
    for (int i = 0; i < 8; i++) {
        int gr = bm + ty + i;
        if (gr < N_NODES) {
            *(float4*)&g_xw[gr * CH + bn + tx] =
                make_float4(acc[i][0], acc[i][1], acc[i][2], acc[i][3]);
            *(float4*)&g_xw[gr * CH + bn + tx + 4] =
                make_float4(acc[i][4], acc[i][5], acc[i][6], acc[i][7]);
        }
    }
}

// ---------------- fused gather + self-loop + relu + node-sum --------------------
// One warp per node; lane owns 8 channels (c = lane*8 .. +7) held in registers.
__global__ void __launch_bounds__(256) k_gather(const float* __restrict__ conv_b) {
    const int lane = threadIdx.x & 31;
    const int warp = (blockIdx.x * blockDim.x + threadIdx.x) >> 5;
    const int nwarps = (gridDim.x * blockDim.x) >> 5;
    const int c = lane << 3;

    float4 b0 = *(const float4*)&conv_b[c];
    float4 b1 = *(const float4*)&conv_b[c + 4];

    float hs[8] = {0.f, 0.f, 0.f, 0.f, 0.f, 0.f, 0.f, 0.f};

    for (int n = warp; n < N_NODES; n += nwarps) {
        float acc[8] = {0.f, 0.f, 0.f, 0.f, 0.f, 0.f, 0.f, 0.f};
        const int beg = g_rowptr[n];
        const int cnt = g_cnt[n];
        const float dn = g_dinv[n];

        for (int k = 0; k < cnt; k++) {
            int s = g_csr_src[beg + k];
            float coef = g_csr_coef[beg + k];
            const float4* p = (const float4*)&g_xw[s * CH + c];
            float4 v0 = p[0], v1 = p[1];
            acc[0] += coef * v0.x; acc[1] += coef * v0.y;
            acc[2] += coef * v0.z; acc[3] += coef * v0.w;
            acc[4] += coef * v1.x; acc[5] += coef * v1.y;
            acc[6] += coef * v1.z; acc[7] += coef * v1.w;
        }
        // self loop: dinv[n]^2 * xw[n]
        {
            const float4* p = (const float4*)&g_xw[n * CH + c];
            float4 v0 = p[0], v1 = p[1];
            float c2 = dn * dn;
            acc[0] += c2 * v0.x; acc[1] += c2 * v0.y;
            acc[2] += c2 * v0.z; acc[3] += c2 * v0.w;
            acc[4] += c2 * v1.x; acc[5] += c2 * v1.y;
            acc[6] += c2 * v1.z; acc[7] += c2 * v1.w;
        }
        hs[0] += fmaxf(acc[0] + b0.x, 0.f);
        hs[1] += fmaxf(acc[1] + b0.y, 0.f);
        hs[2] += fmaxf(acc[2] + b0.z, 0.f);
        hs[3] += fmaxf(acc[3] + b0.w, 0.f);
        hs[4] += fmaxf(acc[4] + b1.x, 0.f);
        hs[5] += fmaxf(acc[5] + b1.y, 0.f);
        hs[6] += fmaxf(acc[6] + b1.z, 0.f);
        hs[7] += fmaxf(acc[7] + b1.w, 0.f);
    }
    #pragma unroll
    for (int i = 0; i < 8; i++) atomicAdd(&g_s[c + i], hs[i]);
}

// ---------------- 4 tanh GEMVs ---------------------------------------------------
__global__ void k_gemv(const float* __restrict__ fc1w, const float* __restrict__ fc1b,
                       const float* __restrict__ fc2w, const float* __restrict__ fc2b,
                       const float* __restrict__ fc3w, const float* __restrict__ fc3b,
                       const float* __restrict__ fc4w, const float* __restrict__ fc4b,
                       float* __restrict__ out) {
    __shared__ float ss[CH];
    const int t = threadIdx.x;           // 0..767
    if (t < CH) ss[t] = g_s[t];
    __syncthreads();

    const float* w; const float* bb; int row;
    if (t < 256)      { w = fc1w; bb = fc1b; row = t; }
    else if (t < 512) { w = fc2w; bb = fc2b; row = t - 256; }
    else if (t < 640) { w = fc3w; bb = fc3b; row = t - 512; }
    else              { w = fc4w; bb = fc4b; row = t - 640; }

    float acc = bb[row];
    const float4* wr = (const float4*)(w + row * CH);
    #pragma unroll
    for (int k = 0; k < CH / 4; k++) {
        float4 wv = wr[k];
        acc += ss[4 * k + 0] * wv.x + ss[4 * k + 1] * wv.y +
               ss[4 * k + 2] * wv.z + ss[4 * k + 3] * wv.w;
    }
    out[t] = tanhf(acc);
}

// ---------------- launch ---------------------------------------------------------
extern "C" void kernel_launch(void* const* d_in, const int* in_sizes, int n_in,
                              void* d_out, int out_size) {
    const float* x      = (const float*)d_in[0];
    const int*   ei     = (const int*)  d_in[1];
    const float* conv_w = (const float*)d_in[2];
    const float* conv_b = (const float*)d_in[3];
    const float* fc1w   = (const float*)d_in[4];
    const float* fc1b   = (const float*)d_in[5];
    const float* fc2w   = (const float*)d_in[6];
    const float* fc2b   = (const float*)d_in[7];
    const float* fc3w   = (const float*)d_in[8];
    const float* fc3b   = (const float*)d_in[9];
    const float* fc4w   = (const float*)d_in[10];
    const float* fc4b   = (const float*)d_in[11];
    float* out = (float*)d_out;

    const int* src = ei;
    const int* dst = ei + N_EDGES;

    k_init0<<<NSCAN, 256>>>();
    k_count<<<(N_EDGES + 255) / 256, 256>>>(src, dst);
    k_dinv<<<NSCAN, 256>>>();
    k_scan1<<<NSCAN, 256>>>();
    k_scan2<<<1, 256>>>();
    k_scan3<<<NSCAN, 256>>>();
    k_fill<<<(N_EDGES + 255) / 256, 256>>>(src, dst);

    dim3 gg((N_NODES + BM - 1) / BM, CH / BN);
    k_gemm<<<gg, 256>>>(x, conv_w);

    k_gather<<<1024, 256>>>(conv_b);

    k_gemv<<<1, 768>>>(fc1w, fc1b, fc2w, fc2b, fc3w, fc3b, fc4w, fc4b, out);
}

// round 3
// speedup vs baseline: 1.5961x; 1.5961x over previous
#include <cuda_runtime.h>

#define N_NODES 50000
#define CH      256
#define N_EDGES 800000
#define NSCAN   196          // ceil(50000/256)

// ---------------- scratch (device globals) ------------------------------------
__device__ float g_xw  [N_NODES * CH];   // x @ conv_w  (51.2 MB, L2-resident)
__device__ float g_dinv[N_NODES];
__device__ int   g_sdeg[N_NODES];        // src degree (incl self-loop)
__device__ int   g_cnt [N_NODES];        // dst degree (excl self-loop)
__device__ int   g_rowptr[N_NODES];
__device__ int   g_cursor[N_NODES];
__device__ int   g_bsum[NSCAN];
__device__ int   g_csr_src [N_EDGES];
__device__ float g_csr_coef[N_EDGES];
__device__ float g_s[CH];

// ---------------- init ---------------------------------------------------------
__global__ void k_init0() {
    int i = blockIdx.x * blockDim.x + threadIdx.x;
    if (i < N_NODES) { g_sdeg[i] = 1; g_cnt[i] = 0; }
    if (i < CH)      g_s[i] = 0.0f;
}

// ---------------- histograms -----------------------------------------------------
__global__ void k_count(const int* __restrict__ src, const int* __restrict__ dst) {
    int e = blockIdx.x * blockDim.x + threadIdx.x;
    if (e < N_EDGES) {
        atomicAdd(&g_sdeg[src[e]], 1);
        atomicAdd(&g_cnt[dst[e]], 1);
    }
}

__global__ void k_dinv() {
    int i = blockIdx.x * blockDim.x + threadIdx.x;
    if (i < N_NODES) g_dinv[i] = rsqrtf((float)g_sdeg[i]);
}

// ---------------- 3-kernel exclusive scan over g_cnt ----------------------------
__global__ void k_scan1() {
    __shared__ int sh[256];
    int t = threadIdx.x, i = blockIdx.x * 256 + t;
    int v = (i < N_NODES) ? g_cnt[i] : 0;
    sh[t] = v; __syncthreads();
    #pragma unroll
    for (int off = 1; off < 256; off <<= 1) {
        int add = (t >= off) ? sh[t - off] : 0;
        __syncthreads();
        sh[t] += add;
        __syncthreads();
    }
    if (i < N_NODES) g_rowptr[i] = sh[t] - v;   // exclusive
    if (t == 255) g_bsum[blockIdx.x] = sh[255];
}

__global__ void k_scan2() {
    __shared__ int sh[256];
    int t = threadIdx.x;
    int v = (t < NSCAN) ? g_bsum[t] : 0;
    sh[t] = v; __syncthreads();
    #pragma unroll
    for (int off = 1; off < 256; off <<= 1) {
        int add = (t >= off) ? sh[t - off] : 0;
        __syncthreads();
        sh[t] += add;
        __syncthreads();
    }
    if (t < NSCAN) g_bsum[t] = sh[t] - v;       // exclusive
}

__global__ void k_scan3() {
    int i = blockIdx.x * blockDim.x + threadIdx.x;
    if (i < N_NODES) {
        int r = g_rowptr[i] + g_bsum[i >> 8];
        g_rowptr[i] = r;
        g_cursor[i] = r;
    }
}

// ---------------- CSR fill (also precompute edge coefficient) --------------------
__global__ void k_fill(const int* __restrict__ src, const int* __restrict__ dst) {
    int e = blockIdx.x * blockDim.x + threadIdx.x;
    if (e < N_EDGES) {
        int s = src[e], d = dst[e];
        int pos = atomicAdd(&g_cursor[d], 1);
        g_csr_src[pos]  = s;
        g_csr_coef[pos] = g_dinv[s] * g_dinv[d];
    }
}

// ---------------- SGEMM: g_xw[M,256] = x[M,256] @ W[256,256] ---------------------
#define BM 128
#define BN 128
#define BK 16
__global__ void __launch_bounds__(256) k_gemm(const float* __restrict__ A,
                                              const float* __restrict__ W) {
    __shared__ float As[BK][BM];
    __shared__ float Bs[BK][BN];
    const int tid = threadIdx.x;
    const int bm = blockIdx.x * BM;
    const int bn = blockIdx.y * BN;

    const int a_row = tid >> 2;            // 0..63 (and +64)
    const int a_col = (tid & 3) << 2;      // 0,4,8,12
    const int b_row = tid >> 4;            // 0..15
    const int b_col = (tid & 15) << 3;     // 0..120 step 8

    const int ty = (tid >> 4) << 3;
    const int tx = (tid & 15) << 3;

    float acc[8][8];
    #pragma unroll
    for (int i = 0; i < 8; i++)
        #pragma unroll
        for (int j = 0; j < 8; j++) acc[i][j] = 0.f;

    for (int k0 = 0; k0 < CH; k0 += BK) {
        #pragma unroll
        for (int h = 0; h < 2; h++) {
            int r = a_row + h * 64;
            int gr = bm + r;
            float4 av = make_float4(0.f, 0.f, 0.f, 0.f);
            if (gr < N_NODES) av = *(const float4*)&A[gr * CH + k0 + a_col];
            As[a_col + 0][r] = av.x;
            As[a_col + 1][r] = av.y;
            As[a_col + 2][r] = av.z;
            As[a_col + 3][r] = av.w;
        }
        *(float4*)&Bs[b_row][b_col] =
            *(const float4*)&W[(k0 + b_row) * CH + bn + b_col];
        *(float4*)&Bs[b_row][b_col + 4] =
            *(const float4*)&W[(k0 + b_row) * CH + bn + b_col + 4];
        __syncthreads();
        #pragma unroll
        for (int k = 0; k < BK; k++) {
            float ar[8], br[8];
            #pragma unroll
            for (int i = 0; i < 8; i++) ar[i] = As[k][ty + i];
            #pragma unroll
            for (int j = 0; j < 8; j++) br[j] = Bs[k][tx + j];
            #pragma unroll
            for (int i = 0; i < 8; i++)
                #pragma unroll
                for (int j = 0; j < 8; j++) acc[i][j] += ar[i] * br[j];
        }
        __syncthreads();
    }
    #pragma unroll
    for (int i = 0; i < 8; i++) {
        int gr = bm + ty + i;
        if (gr < N_NODES) {
            *(float4*)&g_xw[gr * CH + bn + tx] =
                make_float4(acc[i][0], acc[i][1], acc[i][2], acc[i][3]);
            *(float4*)&g_xw[gr * CH + bn + tx + 4] =
                make_float4(acc[i][4], acc[i][5], acc[i][6], acc[i][7]);
        }
    }
}

// ---------------- fused gather + self-loop + relu + node-sum ---------------------
// 2 warps per node (128 channels each). Lane owns 4 channels (one float4).
// Edge metadata is loaded 8-at-a-time by lanes 0..7 and broadcast via shfl,
// giving 8 independent gather loads in flight per lane (MLP=8).
#define GATHER_BLOCKS 1184   // 148 SMs * 8 blocks -> 9472 warps = 1 full wave
__global__ void __launch_bounds__(256) k_gather(const float* __restrict__ conv_b) {
    const int lane = threadIdx.x & 31;
    const int warp = (blockIdx.x * blockDim.x + threadIdx.x) >> 5;
    const int nwarps = (GATHER_BLOCKS * 256) >> 5;       // even
    const int half = warp & 1;                            // invariant across stride
    const int c = (half << 7) + (lane << 2);              // fixed channels

    const float4 b = *(const float4*)&conv_b[c];
    float hs0 = 0.f, hs1 = 0.f, hs2 = 0.f, hs3 = 0.f;

    for (int w = warp; w < 2 * N_NODES; w += nwarps) {
        const int n = w >> 1;
        float a0 = 0.f, a1 = 0.f, a2 = 0.f, a3 = 0.f;
        const int beg = g_rowptr[n];
        const int cnt = g_cnt[n];

        int k = 0;
        for (; k + 8 <= cnt; k += 8) {
            int   s_l  = 0;
            float cf_l = 0.f;
            if (lane < 8) {
                s_l  = g_csr_src [beg + k + lane];
                cf_l = g_csr_coef[beg + k + lane];
            }
            #pragma unroll
            for (int j = 0; j < 8; j++) {
                int   s  = __shfl_sync(0xffffffff, s_l,  j);
                float cf = __shfl_sync(0xffffffff, cf_l, j);
                float4 v = *(const float4*)&g_xw[s * CH + c];
                a0 += cf * v.x; a1 += cf * v.y; a2 += cf * v.z; a3 += cf * v.w;
            }
        }
        // remainder (< 8 edges), still batched
        if (k < cnt) {
            int rem = cnt - k;
            int   s_l  = 0;
            float cf_l = 0.f;
            if (lane < rem) {
                s_l  = g_csr_src [beg + k + lane];
                cf_l = g_csr_coef[beg + k + lane];
            }
            for (int j = 0; j < rem; j++) {
                int   s  = __shfl_sync(0xffffffff, s_l,  j);
                float cf = __shfl_sync(0xffffffff, cf_l, j);
                float4 v = *(const float4*)&g_xw[s * CH + c];
                a0 += cf * v.x; a1 += cf * v.y; a2 += cf * v.z; a3 += cf * v.w;
            }
        }
        // self loop: dinv[n]^2 * xw[n]
        {
            float dn = g_dinv[n];
            float c2 = dn * dn;
            float4 v = *(const float4*)&g_xw[n * CH + c];
            a0 += c2 * v.x; a1 += c2 * v.y; a2 += c2 * v.z; a3 += c2 * v.w;
        }
        hs0 += fmaxf(a0 + b.x, 0.f);
        hs1 += fmaxf(a1 + b.y, 0.f);
        hs2 += fmaxf(a2 + b.z, 0.f);
        hs3 += fmaxf(a3 + b.w, 0.f);
    }
    atomicAdd(&g_s[c + 0], hs0);
    atomicAdd(&g_s[c + 1], hs1);
    atomicAdd(&g_s[c + 2], hs2);
    atomicAdd(&g_s[c + 3], hs3);
}

// ---------------- 4 tanh GEMVs -----------------------------------------------------
__global__ void k_gemv(const float* __restrict__ fc1w, const float* __restrict__ fc1b,
                       const float* __restrict__ fc2w, const float* __restrict__ fc2b,
                       const float* __restrict__ fc3w, const float* __restrict__ fc3b,
                       const float* __restrict__ fc4w, const float* __restrict__ fc4b,
                       float* __restrict__ out) {
    __shared__ float ss[CH];
    const int t = threadIdx.x;           // 0..767
    if (t < CH) ss[t] = g_s[t];
    __syncthreads();

    const float* w; const float* bb; int row;
    if (t < 256)      { w = fc1w; bb = fc1b; row = t; }
    else if (t < 512) { w = fc2w; bb = fc2b; row = t - 256; }
    else if (t < 640) { w = fc3w; bb = fc3b; row = t - 512; }
    else              { w = fc4w; bb = fc4b; row = t - 640; }

    float acc = bb[row];
    const float4* wr = (const float4*)(w + row * CH);
    #pragma unroll
    for (int k = 0; k < CH / 4; k++) {
        float4 wv = wr[k];
        acc += ss[4 * k + 0] * wv.x + ss[4 * k + 1] * wv.y +
               ss[4 * k + 2] * wv.z + ss[4 * k + 3] * wv.w;
    }
    out[t] = tanhf(acc);
}

// ---------------- launch -------------------------------------------------------------
extern "C" void kernel_launch(void* const* d_in, const int* in_sizes, int n_in,
                              void* d_out, int out_size) {
    const float* x      = (const float*)d_in[0];
    const int*   ei     = (const int*)  d_in[1];
    const float* conv_w = (const float*)d_in[2];
    const float* conv_b = (const float*)d_in[3];
    const float* fc1w   = (const float*)d_in[4];
    const float* fc1b   = (const float*)d_in[5];
    const float* fc2w   = (const float*)d_in[6];
    const float* fc2b   = (const float*)d_in[7];
    const float* fc3w   = (const float*)d_in[8];
    const float* fc3b   = (const float*)d_in[9];
    const float* fc4w   = (const float*)d_in[10];
    const float* fc4b   = (const float*)d_in[11];
    float* out = (float*)d_out;

    const int* src = ei;
    const int* dst = ei + N_EDGES;

    k_init0<<<NSCAN, 256>>>();
    k_count<<<(N_EDGES + 255) / 256, 256>>>(src, dst);
    k_dinv<<<NSCAN, 256>>>();
    k_scan1<<<NSCAN, 256>>>();
    k_scan2<<<1, 256>>>();
    k_scan3<<<NSCAN, 256>>>();
    k_fill<<<(N_EDGES + 255) / 256, 256>>>(src, dst);

    dim3 gg((N_NODES + BM - 1) / BM, CH / BN);
    k_gemm<<<gg, 256>>>(x, conv_w);

    k_gather<<<GATHER_BLOCKS, 256>>>(conv_b);

    k_gemv<<<1, 768>>>(fc1w, fc1b, fc2w, fc2b, fc3w, fc3b, fc4w, fc4b, out);
}

// round 5
// speedup vs baseline: 1.6045x; 1.0053x over previous
#include <cuda_runtime.h>
#include <cuda_bf16.h>
#include <cstdint>

#define N_NODES 50000
#define CH      256
#define N_EDGES 800000
#define NSCAN   196          // ceil(50000/256)

// ---------------- scratch (device globals) ------------------------------------
__device__ float g_xw  [N_NODES * CH];   // x @ conv_w  (51.2 MB, L2-resident)
__device__ float g_dinv[N_NODES];
__device__ int   g_sdeg[N_NODES];        // src degree (incl self-loop)
__device__ int   g_cnt [N_NODES];        // dst degree (excl self-loop)
__device__ int   g_rowptr[N_NODES];
__device__ int   g_cursor[N_NODES];
__device__ int   g_bsum[NSCAN];
__device__ int   g_csr_src [N_EDGES];
__device__ float g_csr_coef[N_EDGES];
__device__ float g_s[CH];

// ---------------- init ---------------------------------------------------------
__global__ void k_init0() {
    int i = blockIdx.x * blockDim.x + threadIdx.x;
    if (i < N_NODES) { g_sdeg[i] = 1; g_cnt[i] = 0; }
    if (i < CH)      g_s[i] = 0.0f;
}

// ---------------- histograms -----------------------------------------------------
__global__ void k_count(const int* __restrict__ src, const int* __restrict__ dst) {
    int e = blockIdx.x * blockDim.x + threadIdx.x;
    if (e < N_EDGES) {
        atomicAdd(&g_sdeg[src[e]], 1);
        atomicAdd(&g_cnt[dst[e]], 1);
    }
}

__global__ void k_dinv() {
    int i = blockIdx.x * blockDim.x + threadIdx.x;
    if (i < N_NODES) g_dinv[i] = rsqrtf((float)g_sdeg[i]);
}

// ---------------- 3-kernel exclusive scan over g_cnt ----------------------------
__global__ void k_scan1() {
    __shared__ int sh[256];
    int t = threadIdx.x, i = blockIdx.x * 256 + t;
    int v = (i < N_NODES) ? g_cnt[i] : 0;
    sh[t] = v; __syncthreads();
    #pragma unroll
    for (int off = 1; off < 256; off <<= 1) {
        int add = (t >= off) ? sh[t - off] : 0;
        __syncthreads();
        sh[t] += add;
        __syncthreads();
    }
    if (i < N_NODES) g_rowptr[i] = sh[t] - v;   // exclusive
    if (t == 255) g_bsum[blockIdx.x] = sh[255];
}

__global__ void k_scan2() {
    __shared__ int sh[256];
    int t = threadIdx.x;
    int v = (t < NSCAN) ? g_bsum[t] : 0;
    sh[t] = v; __syncthreads();
    #pragma unroll
    for (int off = 1; off < 256; off <<= 1) {
        int add = (t >= off) ? sh[t - off] : 0;
        __syncthreads();
        sh[t] += add;
        __syncthreads();
    }
    if (t < NSCAN) g_bsum[t] = sh[t] - v;       // exclusive
}

__global__ void k_scan3() {
    int i = blockIdx.x * blockDim.x + threadIdx.x;
    if (i < N_NODES) {
        int r = g_rowptr[i] + g_bsum[i >> 8];
        g_rowptr[i] = r;
        g_cursor[i] = r;
    }
}

// ---------------- CSR fill (also precompute edge coefficient) --------------------
__global__ void k_fill(const int* __restrict__ src, const int* __restrict__ dst) {
    int e = blockIdx.x * blockDim.x + threadIdx.x;
    if (e < N_EDGES) {
        int s = src[e], d = dst[e];
        int pos = atomicAdd(&g_cursor[d], 1);
        g_csr_src[pos]  = s;
        g_csr_coef[pos] = g_dinv[s] * g_dinv[d];
    }
}

// =================================================================================
// Split-bf16 tensor-core GEMM via mma.sync (sm_80+ path; sm_103 base target OK):
//   g_xw[M,256] = X[M,256] @ W[256,256]
//   X = Xhi + Xlo, W = Whi + Wlo (bf16);  D = Xhi*Whi + Xhi*Wlo + Xlo*Whi (fp32 acc)
// CTA tile 128x128, 8 warps in 4(M) x 2(N), warp tile 32x64, K chunk 32.
// =================================================================================
#define TB_M 128
#define TB_N 128
#define TB_K 32
#define APAD 40   // padded row stride (bf16 elems) -> conflict-free frag loads

__device__ __forceinline__ void mma16816(float* c, const uint32_t* a, const uint32_t* b) {
    asm volatile(
        "mma.sync.aligned.m16n8k16.row.col.f32.bf16.bf16.f32 "
        "{%0,%1,%2,%3}, {%4,%5,%6,%7}, {%8,%9}, {%0,%1,%2,%3};"
        : "+f"(c[0]), "+f"(c[1]), "+f"(c[2]), "+f"(c[3])
        : "r"(a[0]), "r"(a[1]), "r"(a[2]), "r"(a[3]), "r"(b[0]), "r"(b[1]));
}

__global__ void __launch_bounds__(256) k_gemm_mma(const float* __restrict__ X,
                                                  const float* __restrict__ W) {
    __shared__ __nv_bfloat16 Ahi[TB_M][APAD];
    __shared__ __nv_bfloat16 Alo[TB_M][APAD];
    __shared__ __nv_bfloat16 Bhi[TB_N][APAD];   // [n][k] (transposed W)
    __shared__ __nv_bfloat16 Blo[TB_N][APAD];

    const int tid  = threadIdx.x;
    const int wid  = tid >> 5;
    const int lane = tid & 31;
    const int wm   = wid >> 1;          // 0..3
    const int wn   = wid & 1;           // 0..1
    const int bm   = blockIdx.x * TB_M;
    const int n0   = blockIdx.y * TB_N;

    const int qr = lane >> 2;           // 0..7
    const int qc = (lane & 3) << 1;     // 0,2,4,6

    float acc[2][8][4];
    #pragma unroll
    for (int mi = 0; mi < 2; mi++)
        #pragma unroll
        for (int ni = 0; ni < 8; ni++)
            #pragma unroll
            for (int j = 0; j < 4; j++) acc[mi][ni][j] = 0.f;

    for (int k0 = 0; k0 < CH; k0 += TB_K) {
        // ---- load & split X tile [128 x 32] ----
        #pragma unroll
        for (int i = tid; i < TB_M * (TB_K / 4); i += 256) {
            int row = i >> 3;
            int c4  = (i & 7) << 2;
            float4 v = make_float4(0.f, 0.f, 0.f, 0.f);
            int gr = bm + row;
            if (gr < N_NODES) v = *(const float4*)&X[gr * CH + k0 + c4];
            #pragma unroll
            for (int j = 0; j < 4; j++) {
                float f = (j == 0) ? v.x : (j == 1) ? v.y : (j == 2) ? v.z : v.w;
                __nv_bfloat16 h = __float2bfloat16_rn(f);
                Ahi[row][c4 + j] = h;
                Alo[row][c4 + j] = __float2bfloat16_rn(f - __bfloat162float(h));
            }
        }
        // ---- load & split W chunk [32 k x 128 n] -> Bs[n][k] ----
        #pragma unroll
        for (int i = tid; i < TB_K * (TB_N / 4); i += 256) {
            int k  = i >> 5;
            int n4 = (i & 31) << 2;
            float4 v = *(const float4*)&W[(k0 + k) * CH + n0 + n4];
            #pragma unroll
            for (int j = 0; j < 4; j++) {
                float f = (j == 0) ? v.x : (j == 1) ? v.y : (j == 2) ? v.z : v.w;
                __nv_bfloat16 h = __float2bfloat16_rn(f);
                Bhi[n4 + j][k] = h;
                Blo[n4 + j][k] = __float2bfloat16_rn(f - __bfloat162float(h));
            }
        }
        __syncthreads();

        // ---- compute: 2 k-steps of 16 ----
        #pragma unroll
        for (int ks = 0; ks < 2; ks++) {
            const int kk = ks * 16;
            uint32_t ah[2][4], al[2][4];
            #pragma unroll
            for (int mi = 0; mi < 2; mi++) {
                int r0 = wm * 32 + mi * 16;
                ah[mi][0] = *(const uint32_t*)&Ahi[r0 + qr][kk + qc];
                ah[mi][1] = *(const uint32_t*)&Ahi[r0 + qr + 8][kk + qc];
                ah[mi][2] = *(const uint32_t*)&Ahi[r0 + qr][kk + qc + 8];
                ah[mi][3] = *(const uint32_t*)&Ahi[r0 + qr + 8][kk + qc + 8];
                al[mi][0] = *(const uint32_t*)&Alo[r0 + qr][kk + qc];
                al[mi][1] = *(const uint32_t*)&Alo[r0 + qr + 8][kk + qc];
                al[mi][2] = *(const uint32_t*)&Alo[r0 + qr][kk + qc + 8];
                al[mi][3] = *(const uint32_t*)&Alo[r0 + qr + 8][kk + qc + 8];
            }
            uint32_t bh[8][2], bl[8][2];
            #pragma unroll
            for (int ni = 0; ni < 8; ni++) {
                int n = wn * 64 + ni * 8 + qr;
                bh[ni][0] = *(const uint32_t*)&Bhi[n][kk + qc];
                bh[ni][1] = *(const uint32_t*)&Bhi[n][kk + qc + 8];
                bl[ni][0] = *(const uint32_t*)&Blo[n][kk + qc];
                bl[ni][1] = *(const uint32_t*)&Blo[n][kk + qc + 8];
            }
            #pragma unroll
            for (int mi = 0; mi < 2; mi++)
                #pragma unroll
                for (int ni = 0; ni < 8; ni++) {
                    mma16816(acc[mi][ni], ah[mi], bh[ni]);
                    mma16816(acc[mi][ni], ah[mi], bl[ni]);
                    mma16816(acc[mi][ni], al[mi], bh[ni]);
                }
        }
        __syncthreads();
    }

    // ---- epilogue ----
    #pragma unroll
    for (int mi = 0; mi < 2; mi++) {
        int r0 = bm + wm * 32 + mi * 16 + qr;
        #pragma unroll
        for (int ni = 0; ni < 8; ni++) {
            int cg = n0 + wn * 64 + ni * 8 + qc;
            if (r0 < N_NODES)
                *(float2*)&g_xw[r0 * CH + cg] = make_float2(acc[mi][ni][0], acc[mi][ni][1]);
            if (r0 + 8 < N_NODES)
                *(float2*)&g_xw[(r0 + 8) * CH + cg] = make_float2(acc[mi][ni][2], acc[mi][ni][3]);
        }
    }
}

// ---------------- fused gather + self-loop + relu + node-sum ---------------------
#define GATHER_BLOCKS 1184
__global__ void __launch_bounds__(256) k_gather(const float* __restrict__ conv_b) {
    const int lane = threadIdx.x & 31;
    const int warp = (blockIdx.x * blockDim.x + threadIdx.x) >> 5;
    const int nwarps = (GATHER_BLOCKS * 256) >> 5;
    const int half = warp & 1;
    const int c = (half << 7) + (lane << 2);

    const float4 b = *(const float4*)&conv_b[c];
    float hs0 = 0.f, hs1 = 0.f, hs2 = 0.f, hs3 = 0.f;

    for (int w = warp; w < 2 * N_NODES; w += nwarps) {
        const int n = w >> 1;
        float a0 = 0.f, a1 = 0.f, a2 = 0.f, a3 = 0.f;
        const int beg = g_rowptr[n];
        const int cnt = g_cnt[n];

        int k = 0;
        for (; k + 8 <= cnt; k += 8) {
            int   s_l  = 0;
            float cf_l = 0.f;
            if (lane < 8) {
                s_l  = g_csr_src [beg + k + lane];
                cf_l = g_csr_coef[beg + k + lane];
            }
            #pragma unroll
            for (int j = 0; j < 8; j++) {
                int   s  = __shfl_sync(0xffffffff, s_l,  j);
                float cf = __shfl_sync(0xffffffff, cf_l, j);
                float4 v = *(const float4*)&g_xw[s * CH + c];
                a0 += cf * v.x; a1 += cf * v.y; a2 += cf * v.z; a3 += cf * v.w;
            }
        }
        if (k < cnt) {
            int rem = cnt - k;
            int   s_l  = 0;
            float cf_l = 0.f;
            if (lane < rem) {
                s_l  = g_csr_src [beg + k + lane];
                cf_l = g_csr_coef[beg + k + lane];
            }
            for (int j = 0; j < rem; j++) {
                int   s  = __shfl_sync(0xffffffff, s_l,  j);
                float cf = __shfl_sync(0xffffffff, cf_l, j);
                float4 v = *(const float4*)&g_xw[s * CH + c];
                a0 += cf * v.x; a1 += cf * v.y; a2 += cf * v.z; a3 += cf * v.w;
            }
        }
        {
            float dn = g_dinv[n];
            float c2 = dn * dn;
            float4 v = *(const float4*)&g_xw[n * CH + c];
            a0 += c2 * v.x; a1 += c2 * v.y; a2 += c2 * v.z; a3 += c2 * v.w;
        }
        hs0 += fmaxf(a0 + b.x, 0.f);
        hs1 += fmaxf(a1 + b.y, 0.f);
        hs2 += fmaxf(a2 + b.z, 0.f);
        hs3 += fmaxf(a3 + b.w, 0.f);
    }
    atomicAdd(&g_s[c + 0], hs0);
    atomicAdd(&g_s[c + 1], hs1);
    atomicAdd(&g_s[c + 2], hs2);
    atomicAdd(&g_s[c + 3], hs3);
}

// ---------------- 4 tanh GEMVs -----------------------------------------------------
__global__ void k_gemv(const float* __restrict__ fc1w, const float* __restrict__ fc1b,
                       const float* __restrict__ fc2w, const float* __restrict__ fc2b,
                       const float* __restrict__ fc3w, const float* __restrict__ fc3b,
                       const float* __restrict__ fc4w, const float* __restrict__ fc4b,
                       float* __restrict__ out) {
    __shared__ float ss[CH];
    const int t = threadIdx.x;
    if (t < CH) ss[t] = g_s[t];
    __syncthreads();

    const float* w; const float* bb; int row;
    if (t < 256)      { w = fc1w; bb = fc1b; row = t; }
    else if (t < 512) { w = fc2w; bb = fc2b; row = t - 256; }
    else if (t < 640) { w = fc3w; bb = fc3b; row = t - 512; }
    else              { w = fc4w; bb = fc4b; row = t - 640; }

    float acc = bb[row];
    const float4* wr = (const float4*)(w + row * CH);
    #pragma unroll
    for (int k = 0; k < CH / 4; k++) {
        float4 wv = wr[k];
        acc += ss[4 * k + 0] * wv.x + ss[4 * k + 1] * wv.y +
               ss[4 * k + 2] * wv.z + ss[4 * k + 3] * wv.w;
    }
    out[t] = tanhf(acc);
}

// ---------------- launch -------------------------------------------------------------
extern "C" void kernel_launch(void* const* d_in, const int* in_sizes, int n_in,
                              void* d_out, int out_size) {
    const float* x      = (const float*)d_in[0];
    const int*   ei     = (const int*)  d_in[1];
    const float* conv_w = (const float*)d_in[2];
    const float* conv_b = (const float*)d_in[3];
    const float* fc1w   = (const float*)d_in[4];
    const float* fc1b   = (const float*)d_in[5];
    const float* fc2w   = (const float*)d_in[6];
    const float* fc2b   = (const float*)d_in[7];
    const float* fc3w   = (const float*)d_in[8];
    const float* fc3b   = (const float*)d_in[9];
    const float* fc4w   = (const float*)d_in[10];
    const float* fc4b   = (const float*)d_in[11];
    float* out = (float*)d_out;

    const int* src = ei;
    const int* dst = ei + N_EDGES;

    k_init0<<<NSCAN, 256>>>();
    k_count<<<(N_EDGES + 255) / 256, 256>>>(src, dst);
    k_dinv<<<NSCAN, 256>>>();
    k_scan1<<<NSCAN, 256>>>();
    k_scan2<<<1, 256>>>();
    k_scan3<<<NSCAN, 256>>>();
    k_fill<<<(N_EDGES + 255) / 256, 256>>>(src, dst);

    dim3 gg((N_NODES + TB_M - 1) / TB_M, CH / TB_N);
    k_gemm_mma<<<gg, 256>>>(x, conv_w);

    k_gather<<<GATHER_BLOCKS, 256>>>(conv_b);

    k_gemv<<<1, 768>>>(fc1w, fc1b, fc2w, fc2b, fc3w, fc3b, fc4w, fc4b, out);
}